// round 15
// baseline (speedup 1.0000x reference)
#include <cuda_runtime.h>
#include <cuda_bf16.h>
#include <math.h>

// Problem constants (fixed by the reference)
#define NN 50000
#define EE 800000
#define FIN 128
#define ED 16
#define HID 64
#define OUT 128
#define GG 256
#define NEG 0.2f
#define NPAD 53248   // 52*1024, scan padding
#define SCAN_BLOCKS 52

// ---------------- device scratch (static, allocation-free) ----------------
__device__ int   g_deg[NPAD];
__device__ int   g_ptr[NN + 4];
__device__ int   g_cursor[NN];
__device__ int   g_bflag[SCAN_BLOCKS];       // lookback flags: bit30 = published
__device__ int   g_srcCSR[EE];
__device__ float g_alE1[EE * 8];     // per CSR slot, 8 heads (edge-only logit, layer1)
__device__ float g_alE2[EE];         // per CSR slot (edge-only logit, layer2)
__device__ __nv_bfloat162 g_xw1b[NN * 32];   // xw1 values, bf16 (64 feats/node)
__device__ float g_als1[NN * 8];
__device__ float g_ald1[NN * 8];
__device__ float g_h[NN * HID];              // layer-1 output (post ELU), fp32
__device__ __nv_bfloat162 g_xw2b[NN * 64];   // xw2 values, bf16 (128 feats/node)
__device__ float g_als2[NN];
__device__ float g_ald2[NN];
__device__ float g_out2[NN * OUT];
__device__ float g_M1[ED * 8];
__device__ float g_m2[ED];
__device__ int   g_gptr[GG + 1];

// Side stream + fork/join events (host-side resources only).
static cudaStream_t g_s2 = 0;
static cudaEvent_t  g_evF = 0, g_evJ = 0;
namespace {
struct StreamInit {
    StreamInit() {
        cudaStreamCreateWithFlags(&g_s2, cudaStreamNonBlocking);
        cudaEventCreateWithFlags(&g_evF, cudaEventDisableTiming);
        cudaEventCreateWithFlags(&g_evJ, cudaEventDisableTiming);
    }
};
StreamInit g_stream_init;
}

// packed fp32x2 FMA (sm_10x)
__device__ __forceinline__ void ffma2(unsigned long long& d,
                                      unsigned long long a, unsigned long long b) {
    asm("fma.rn.f32x2 %0, %1, %2, %0;" : "+l"(d) : "l"(a), "l"(b));
}
__device__ __forceinline__ unsigned long long pack2(float v) {
    unsigned long long r;
    asm("mov.b64 %0, {%1, %1};" : "=l"(r) : "r"(__float_as_uint(v)));
    return r;
}
__device__ __forceinline__ float2 unpack2(unsigned long long p) {
    unsigned int lo, hi;
    asm("mov.b64 {%0, %1}, %2;" : "=r"(lo), "=r"(hi) : "l"(p));
    return make_float2(__uint_as_float(lo), __uint_as_float(hi));
}
__device__ __forceinline__ void st_release(int* p, int v) {
    asm volatile("st.global.release.gpu.b32 [%0], %1;" :: "l"(p), "r"(v) : "memory");
}
__device__ __forceinline__ int ld_acquire(const int* p) {
    int v;
    asm volatile("ld.global.acquire.gpu.b32 %0, [%1];" : "=r"(v) : "l"(p) : "memory");
    return v;
}

// ---------------- kernels ----------------

// Fused setup: zero padded deg + scan flags + reduced attention matrices + graph offsets.
__global__ void setup_kernel(const float* __restrict__ We1, const float* __restrict__ ae1,
                             const float* __restrict__ We2, const float* __restrict__ ae2,
                             const int* __restrict__ batch) {
    int i = blockIdx.x * blockDim.x + threadIdx.x;
    if (i < NPAD) g_deg[i] = 0;
    if (i < SCAN_BLOCKS) g_bflag[i] = 0;
    if (i < 128) {
        int d = i >> 3, h = i & 7;
        float s = 0.f;
        #pragma unroll
        for (int c = 0; c < 8; c++) s += We1[d * 64 + h * 8 + c] * ae1[h * 8 + c];
        g_M1[d * 8 + h] = s;
    }
    if (i < ED) {
        float s = 0.f;
        for (int c = 0; c < OUT; c++) s += We2[i * OUT + c] * ae2[c];
        g_m2[i] = s;
    }
    if (i <= GG) {
        if (i == GG) g_gptr[GG] = NN;
        else {
            int lo = 0, hi = NN;
            while (lo < hi) {
                int mid = (lo + hi) >> 1;
                if (batch[mid] < i) lo = mid + 1; else hi = mid;
            }
            g_gptr[i] = lo;
        }
    }
}

// Degree count: int4 dst load, 4 independent RED chains per thread.
__global__ void deg_kernel(const int* __restrict__ ei) {
    int e4 = blockIdx.x * blockDim.x + threadIdx.x;
    if (e4 < EE / 4) {
        int4 d = ((const int4*)(ei + EE))[e4];
        atomicAdd(&g_deg[d.x], 1);
        atomicAdd(&g_deg[d.y], 1);
        atomicAdd(&g_deg[d.z], 1);
        atomicAdd(&g_deg[d.w], 1);
    }
}

// Parallel exclusive scan, decoupled lookback. 52 blocks x 1024 threads.
__global__ __launch_bounds__(1024) void scan_kernel() {
    int b = blockIdx.x, t = threadIdx.x;
    int gi = b * 1024 + t;
    int v = g_deg[gi];
    int incl = v;
    #pragma unroll
    for (int o = 1; o < 32; o <<= 1) {
        int u = __shfl_up_sync(0xffffffffu, incl, o);
        if ((t & 31) >= o) incl += u;
    }
    __shared__ int ws[32];
    __shared__ int s_tot, s_off;
    if ((t & 31) == 31) ws[t >> 5] = incl;
    __syncthreads();
    if (t < 32) {
        int wv = ws[t];
        int wincl = wv;
        #pragma unroll
        for (int o = 1; o < 32; o <<= 1) {
            int u = __shfl_up_sync(0xffffffffu, wincl, o);
            if (t >= o) wincl += u;
        }
        ws[t] = wincl - wv;
        if (t == 31) s_tot = wincl;
    }
    __syncthreads();
    if (t == 0) st_release(&g_bflag[b], s_tot | 0x40000000);
    if (t < 32) {
        int acc = 0;
        for (int p = t; p < b; p += 32) {
            int f;
            do { f = ld_acquire(&g_bflag[p]); } while (!(f & 0x40000000));
            acc += f & 0x3FFFFFFF;
        }
        #pragma unroll
        for (int o = 16; o > 0; o >>= 1) acc += __shfl_xor_sync(0xffffffffu, acc, o);
        if (t == 0) s_off = acc;
    }
    __syncthreads();
    int ptr = s_off + ws[t >> 5] + (incl - v);
    if (gi < NN) {
        g_ptr[gi] = ptr;
        g_cursor[gi] = ptr;
    }
    if (gi == NN) g_ptr[NN] = EE;
}

// Fused CSR scatter + edge-logit compute (f32x2-packed head math). 4 edges/thread.
__global__ __launch_bounds__(256) void scatter_kernel(const int* __restrict__ ei,
                                                      const float* __restrict__ ea) {
    __shared__ float sM1[ED * 8];
    __shared__ float sm2[ED];
    if (threadIdx.x < 128) sM1[threadIdx.x] = g_M1[threadIdx.x];
    if (threadIdx.x < ED) sm2[threadIdx.x] = g_m2[threadIdx.x];
    __syncthreads();
    int e4 = blockIdx.x * blockDim.x + threadIdx.x;
    if (e4 >= EE / 4) return;
    int4 s4 = ((const int4*)ei)[e4];
    int4 d4 = ((const int4*)(ei + EE))[e4];
    int srcs[4] = {s4.x, s4.y, s4.z, s4.w};
    int dsts[4] = {d4.x, d4.y, d4.z, d4.w};
    int pos[4];
    #pragma unroll
    for (int k = 0; k < 4; k++)
        pos[k] = atomicAdd(&g_cursor[dsts[k]], 1);
    const unsigned long long* sM1p = (const unsigned long long*)sM1;
    #pragma unroll
    for (int k = 0; k < 4; k++) {
        int e = e4 * 4 + k;
        const float4* p = (const float4*)(ea + (size_t)e * ED);
        float4 q0 = p[0], q1 = p[1], q2 = p[2], q3 = p[3];
        float av[16] = {q0.x, q0.y, q0.z, q0.w, q1.x, q1.y, q1.z, q1.w,
                        q2.x, q2.y, q2.z, q2.w, q3.x, q3.y, q3.z, q3.w};
        unsigned long long r01 = 0ull, r23 = 0ull, r45 = 0ull, r67 = 0ull;
        float r2 = 0.f;
        #pragma unroll
        for (int d = 0; d < ED; d++) {
            float a = av[d];
            unsigned long long ap = pack2(a);
            ffma2(r01, ap, sM1p[d * 4 + 0]);
            ffma2(r23, ap, sM1p[d * 4 + 1]);
            ffma2(r45, ap, sM1p[d * 4 + 2]);
            ffma2(r67, ap, sM1p[d * 4 + 3]);
            r2 += a * sm2[d];
        }
        int pk = pos[k];
        g_srcCSR[pk] = srcs[k];
        float2 f01 = unpack2(r01), f23 = unpack2(r23);
        float2 f45 = unpack2(r45), f67 = unpack2(r67);
        float4* o = (float4*)(g_alE1 + (size_t)pk * 8);
        o[0] = make_float4(f01.x, f01.y, f23.x, f23.y);
        o[1] = make_float4(f45.x, f45.y, f67.x, f67.y);
        g_alE2[pk] = r2;
    }
}

// xw1 = x @ W1 (bf16 out), plus per-node attention scalars als1/ald1 (fp32).
#define G1_NODES 64
__global__ __launch_bounds__(256) void gemm1_kernel(const float* __restrict__ x,
                             const float* __restrict__ W1,
                             const float* __restrict__ as1, const float* __restrict__ ad1) {
    __shared__ float xs[G1_NODES][FIN + 4];
    int n0 = blockIdx.x * G1_NODES;
    for (int idx = threadIdx.x; idx < G1_NODES * (FIN / 4); idx += 256) {
        int row = idx >> 5;
        int c4  = idx & 31;
        int n = n0 + row; if (n >= NN) n = NN - 1;
        float4 v = ((const float4*)(x + (size_t)n * FIN))[c4];
        *(float4*)&xs[row][c4 * 4] = v;
    }
    __syncthreads();
    int jg = threadIdx.x & 15;
    int ng = threadIdx.x >> 4;
    const ulonglong2* W1v = (const ulonglong2*)W1;
    unsigned long long a0[4], a1[4];
    #pragma unroll
    for (int i = 0; i < 4; i++) { a0[i] = 0ull; a1[i] = 0ull; }
    #pragma unroll 4
    for (int k = 0; k < FIN; k++) {
        ulonglong2 w = W1v[k * 16 + jg];
        #pragma unroll
        for (int i = 0; i < 4; i++) {
            unsigned long long xv = pack2(xs[ng * 4 + i][k]);
            ffma2(a0[i], xv, w.x);
            ffma2(a1[i], xv, w.y);
        }
    }
    float4 a_s = ((const float4*)as1)[jg];
    float4 a_d = ((const float4*)ad1)[jg];
    #pragma unroll
    for (int i = 0; i < 4; i++) {
        int n = n0 + ng * 4 + i;
        if (n >= NN) break;
        float2 lo = unpack2(a0[i]);
        float2 hi = unpack2(a1[i]);
        __nv_bfloat162 c0 = __float22bfloat162_rn(lo);
        __nv_bfloat162 c1 = __float22bfloat162_rn(hi);
        uint2 pk;
        pk.x = *(unsigned int*)&c0;
        pk.y = *(unsigned int*)&c1;
        ((uint2*)(g_xw1b + (size_t)n * 32))[jg] = pk;
        float ps = lo.x * a_s.x + lo.y * a_s.y + hi.x * a_s.z + hi.y * a_s.w;
        float pd = lo.x * a_d.x + lo.y * a_d.y + hi.x * a_d.z + hi.y * a_d.w;
        ps += __shfl_xor_sync(0xffffffffu, ps, 1);
        pd += __shfl_xor_sync(0xffffffffu, pd, 1);
        if ((threadIdx.x & 1) == 0) {
            int h = jg >> 1;
            g_als1[n * 8 + h] = ps;
            g_ald1[n * 8 + h] = pd;
        }
    }
}

// Layer-1 softmax + aggregation + ELU. One warp per node, head-aligned lanes
// (no shfl), DEPTH-2 software pipeline: src indices 2 groups ahead, gathered
// values 1 group ahead, so consume never waits on a just-issued load.
__global__ __launch_bounds__(256) void agg1_kernel(const float* __restrict__ b1) {
    int warp = (blockIdx.x * blockDim.x + threadIdx.x) >> 5;
    if (warp >= NN) return;
    int n = warp;
    int l = threadIdx.x & 31;
    int h = l >> 2;                            // head for features 2l, 2l+1
    const float* __restrict__ als1 = g_als1;
    const float* __restrict__ alE1 = g_alE1;
    const __nv_bfloat162* __restrict__ xw1b = g_xw1b;
    const int* __restrict__ srcv = g_srcCSR;

    float ald = g_ald1[n * 8 + h];
    float myals = als1[n * 8 + h];
    int beg = g_ptr[n], end = g_ptr[n + 1];

    float s = 0.f, salE = 0.f;
    float acc0 = 0.f, acc1 = 0.f;
    __nv_bfloat162 z2 = __float2bfloat162_rn(0.f);

    int j = beg;
    bool has0 = (j + 3 < end);
    int sc0 = 0, sc1 = 0, sc2 = 0, sc3 = 0;
    float alc0 = 0, alc1 = 0, alc2 = 0, alc3 = 0;
    float aec0 = 0, aec1 = 0, aec2 = 0, aec3 = 0;
    __nv_bfloat162 vc0 = z2, vc1 = z2, vc2 = z2, vc3 = z2;
    if (has0) {
        sc0 = srcv[j]; sc1 = srcv[j + 1]; sc2 = srcv[j + 2]; sc3 = srcv[j + 3];
        alc0 = als1[sc0 * 8 + h]; alc1 = als1[sc1 * 8 + h];
        alc2 = als1[sc2 * 8 + h]; alc3 = als1[sc3 * 8 + h];
        aec0 = alE1[(size_t)j * 8 + h];       aec1 = alE1[(size_t)(j + 1) * 8 + h];
        aec2 = alE1[(size_t)(j + 2) * 8 + h]; aec3 = alE1[(size_t)(j + 3) * 8 + h];
        vc0 = xw1b[(size_t)sc0 * 32 + l]; vc1 = xw1b[(size_t)sc1 * 32 + l];
        vc2 = xw1b[(size_t)sc2 * 32 + l]; vc3 = xw1b[(size_t)sc3 * 32 + l];
    }
    int jn = j + 4;
    bool has1 = has0 && (jn + 3 < end);
    int sn0 = 0, sn1 = 0, sn2 = 0, sn3 = 0;
    if (has1) { sn0 = srcv[jn]; sn1 = srcv[jn + 1]; sn2 = srcv[jn + 2]; sn3 = srcv[jn + 3]; }

    while (has0) {
        // issue next group's gathered values (src already resident)
        float aln0 = 0, aln1 = 0, aln2 = 0, aln3 = 0;
        float aen0 = 0, aen1 = 0, aen2 = 0, aen3 = 0;
        __nv_bfloat162 vn0 = z2, vn1 = z2, vn2 = z2, vn3 = z2;
        if (has1) {
            aln0 = als1[sn0 * 8 + h]; aln1 = als1[sn1 * 8 + h];
            aln2 = als1[sn2 * 8 + h]; aln3 = als1[sn3 * 8 + h];
            aen0 = alE1[(size_t)jn * 8 + h];       aen1 = alE1[(size_t)(jn + 1) * 8 + h];
            aen2 = alE1[(size_t)(jn + 2) * 8 + h]; aen3 = alE1[(size_t)(jn + 3) * 8 + h];
            vn0 = xw1b[(size_t)sn0 * 32 + l]; vn1 = xw1b[(size_t)sn1 * 32 + l];
            vn2 = xw1b[(size_t)sn2 * 32 + l]; vn3 = xw1b[(size_t)sn3 * 32 + l];
        }
        // issue src for group after next
        int jnn = jn + 4;
        bool has2 = has1 && (jnn + 3 < end);
        int snn0 = 0, snn1 = 0, snn2 = 0, snn3 = 0;
        if (has2) { snn0 = srcv[jnn]; snn1 = srcv[jnn + 1]; snn2 = srcv[jnn + 2]; snn3 = srcv[jnn + 3]; }
        // consume current group (values loaded one iteration ago)
        salE += (aec0 + aec1) + (aec2 + aec3);
        float zz0 = alc0 + ald + aec0; zz0 = zz0 > 0.f ? zz0 : NEG * zz0;
        float zz1 = alc1 + ald + aec1; zz1 = zz1 > 0.f ? zz1 : NEG * zz1;
        float zz2 = alc2 + ald + aec2; zz2 = zz2 > 0.f ? zz2 : NEG * zz2;
        float zz3 = alc3 + ald + aec3; zz3 = zz3 > 0.f ? zz3 : NEG * zz3;
        float e0 = __expf(zz0), e1 = __expf(zz1), e2 = __expf(zz2), e3 = __expf(zz3);
        s += (e0 + e1) + (e2 + e3);
        float2 f0 = __bfloat1622float2(vc0);
        float2 f1 = __bfloat1622float2(vc1);
        float2 f2 = __bfloat1622float2(vc2);
        float2 f3 = __bfloat1622float2(vc3);
        acc0 += f0.x * e0 + f1.x * e1;
        acc1 += f0.y * e0 + f1.y * e1;
        acc0 += f2.x * e2 + f3.x * e3;
        acc1 += f2.y * e2 + f3.y * e3;
        // rotate
        j = jn; jn = jnn;
        has0 = has1; has1 = has2;
        alc0 = aln0; alc1 = aln1; alc2 = aln2; alc3 = aln3;
        aec0 = aen0; aec1 = aen1; aec2 = aen2; aec3 = aen3;
        vc0 = vn0; vc1 = vn1; vc2 = vn2; vc3 = vn3;
        sn0 = snn0; sn1 = snn1; sn2 = snn2; sn3 = snn3;
    }
    // tail (fewer than 4 edges remain, starting at j)
    for (; j < end; j++) {
        int sA = srcv[j];
        float alsA = als1[sA * 8 + h];
        float aleA = alE1[(size_t)j * 8 + h];
        __nv_bfloat162 vA = xw1b[(size_t)sA * 32 + l];
        salE += aleA;
        float zA = alsA + ald + aleA; zA = zA > 0.f ? zA : NEG * zA;
        float eA = __expf(zA);
        s += eA;
        float2 fA = __bfloat1622float2(vA);
        acc0 += fA.x * eA; acc1 += fA.y * eA;
    }
    // self loop: edge logit = mean of incoming edge logits
    float rd = 1.f / (float)max(end - beg, 1);
    float zs = myals + ald + salE * rd;
    zs = zs > 0.f ? zs : NEG * zs;
    float es = __expf(zs);
    s += es;
    float2 fS = __bfloat1622float2(xw1b[(size_t)n * 32 + l]);
    acc0 += fS.x * es; acc1 += fS.y * es;
    float2 bb = ((const float2*)b1)[l];
    float o0 = acc0 / (s + 1e-16f) + bb.x;
    float o1 = acc1 / (s + 1e-16f) + bb.y;
    o0 = o0 > 0.f ? o0 : (__expf(o0) - 1.f);   // ELU
    o1 = o1 > 0.f ? o1 : (__expf(o1) - 1.f);
    ((float2*)(g_h + (size_t)n * HID))[l] = make_float2(o0, o1);
}

// xw2 = h @ W2 (bf16 out) + als2/ald2 scalars. 32 nodes/block.
#define G2_NODES 32
__global__ __launch_bounds__(256) void gemm2_kernel(const float* __restrict__ W2,
                             const float* __restrict__ as2, const float* __restrict__ ad2) {
    __shared__ float hs2[G2_NODES][HID + 4];
    __shared__ float s_ps[G2_NODES][8];
    __shared__ float s_pd[G2_NODES][8];
    int n0 = blockIdx.x * G2_NODES;
    for (int idx = threadIdx.x; idx < G2_NODES * (HID / 4); idx += 256) {
        int row = idx >> 4, c4 = idx & 15;
        int n = n0 + row; if (n >= NN) n = NN - 1;
        float4 v = ((const float4*)(g_h + (size_t)n * HID))[c4];
        *(float4*)&hs2[row][c4 * 4] = v;
    }
    __syncthreads();
    int ndl = threadIdx.x & 7;
    int jg  = threadIdx.x >> 3;
    int wid = threadIdx.x >> 5;
    const ulonglong2* W2v = (const ulonglong2*)W2;
    unsigned long long a0[4], a1[4];
    #pragma unroll
    for (int i = 0; i < 4; i++) { a0[i] = 0ull; a1[i] = 0ull; }
    for (int kc = 0; kc < HID; kc += 4) {
        float4 hv4[4];
        #pragma unroll
        for (int i = 0; i < 4; i++)
            hv4[i] = *(const float4*)&hs2[ndl + 8 * i][kc];
        #pragma unroll
        for (int kk = 0; kk < 4; kk++) {
            ulonglong2 w = W2v[(kc + kk) * 32 + jg];
            #pragma unroll
            for (int i = 0; i < 4; i++) {
                unsigned long long hp = pack2(((const float*)&hv4[i])[kk]);
                ffma2(a0[i], hp, w.x);
                ffma2(a1[i], hp, w.y);
            }
        }
    }
    float4 a_s = ((const float4*)as2)[jg];
    float4 a_d = ((const float4*)ad2)[jg];
    #pragma unroll
    for (int i = 0; i < 4; i++) {
        int r = 8 * i + ndl;
        int n = n0 + r;
        float2 lo = unpack2(a0[i]);
        float2 hi = unpack2(a1[i]);
        float ps = lo.x * a_s.x + lo.y * a_s.y + hi.x * a_s.z + hi.y * a_s.w;
        float pd = lo.x * a_d.x + lo.y * a_d.y + hi.x * a_d.z + hi.y * a_d.w;
        ps += __shfl_xor_sync(0xffffffffu, ps, 8);
        pd += __shfl_xor_sync(0xffffffffu, pd, 8);
        ps += __shfl_xor_sync(0xffffffffu, ps, 16);
        pd += __shfl_xor_sync(0xffffffffu, pd, 16);
        if ((threadIdx.x & 24) == 0) {
            s_ps[r][wid] = ps;
            s_pd[r][wid] = pd;
        }
        if (n < NN) {
            __nv_bfloat162 c0 = __float22bfloat162_rn(lo);
            __nv_bfloat162 c1 = __float22bfloat162_rn(hi);
            uint2 pk;
            pk.x = *(unsigned int*)&c0;
            pk.y = *(unsigned int*)&c1;
            ((uint2*)(g_xw2b + (size_t)n * 64))[jg] = pk;
        }
    }
    __syncthreads();
    if (threadIdx.x < G2_NODES) {
        int n = n0 + threadIdx.x;
        if (n < NN) {
            float ps = 0.f, pd = 0.f;
            #pragma unroll
            for (int w = 0; w < 8; w++) { ps += s_ps[threadIdx.x][w]; pd += s_pd[threadIdx.x][w]; }
            g_als2[n] = ps;
            g_ald2[n] = pd;
        }
    }
}

// Layer-2 softmax + aggregation. One warp per node, lane owns features 4l..4l+3,
// DEPTH-2 software pipeline (src 2 ahead, values 1 ahead).
__global__ __launch_bounds__(256) void agg2_kernel(const float* __restrict__ b2) {
    int warp = (blockIdx.x * blockDim.x + threadIdx.x) >> 5;
    if (warp >= NN) return;
    int n = warp;
    int l = threadIdx.x & 31;
    const uint2* __restrict__ xw = (const uint2*)g_xw2b;
    const float* __restrict__ als2 = g_als2;
    const float* __restrict__ alE2 = g_alE2;
    const int*   __restrict__ srcv = g_srcCSR;
    float ald = g_ald2[n];
    float myals = als2[n];
    int beg = g_ptr[n], end = g_ptr[n + 1];
    float s = 0.f, salE = 0.f;
    float4 acc = make_float4(0.f, 0.f, 0.f, 0.f);

    int j = beg;
    bool has0 = (j + 3 < end);
    int sc0 = 0, sc1 = 0, sc2 = 0, sc3 = 0;
    float alc0 = 0, alc1 = 0, alc2 = 0, alc3 = 0;
    float aec0 = 0, aec1 = 0, aec2 = 0, aec3 = 0;
    uint2 uc0 = {0, 0}, uc1 = {0, 0}, uc2 = {0, 0}, uc3 = {0, 0};
    if (has0) {
        sc0 = srcv[j]; sc1 = srcv[j + 1]; sc2 = srcv[j + 2]; sc3 = srcv[j + 3];
        alc0 = als2[sc0]; alc1 = als2[sc1]; alc2 = als2[sc2]; alc3 = als2[sc3];
        aec0 = alE2[j]; aec1 = alE2[j + 1]; aec2 = alE2[j + 2]; aec3 = alE2[j + 3];
        uc0 = xw[(size_t)sc0 * 32 + l]; uc1 = xw[(size_t)sc1 * 32 + l];
        uc2 = xw[(size_t)sc2 * 32 + l]; uc3 = xw[(size_t)sc3 * 32 + l];
    }
    int jn = j + 4;
    bool has1 = has0 && (jn + 3 < end);
    int sn0 = 0, sn1 = 0, sn2 = 0, sn3 = 0;
    if (has1) { sn0 = srcv[jn]; sn1 = srcv[jn + 1]; sn2 = srcv[jn + 2]; sn3 = srcv[jn + 3]; }

    while (has0) {
        float aln0 = 0, aln1 = 0, aln2 = 0, aln3 = 0;
        float aen0 = 0, aen1 = 0, aen2 = 0, aen3 = 0;
        uint2 un0 = {0, 0}, un1 = {0, 0}, un2 = {0, 0}, un3 = {0, 0};
        if (has1) {
            aln0 = als2[sn0]; aln1 = als2[sn1]; aln2 = als2[sn2]; aln3 = als2[sn3];
            aen0 = alE2[jn]; aen1 = alE2[jn + 1]; aen2 = alE2[jn + 2]; aen3 = alE2[jn + 3];
            un0 = xw[(size_t)sn0 * 32 + l]; un1 = xw[(size_t)sn1 * 32 + l];
            un2 = xw[(size_t)sn2 * 32 + l]; un3 = xw[(size_t)sn3 * 32 + l];
        }
        int jnn = jn + 4;
        bool has2 = has1 && (jnn + 3 < end);
        int snn0 = 0, snn1 = 0, snn2 = 0, snn3 = 0;
        if (has2) { snn0 = srcv[jnn]; snn1 = srcv[jnn + 1]; snn2 = srcv[jnn + 2]; snn3 = srcv[jnn + 3]; }
        // consume current group
        salE += (aec0 + aec1) + (aec2 + aec3);
        float zz0 = alc0 + ald + aec0; zz0 = zz0 > 0.f ? zz0 : NEG * zz0;
        float zz1 = alc1 + ald + aec1; zz1 = zz1 > 0.f ? zz1 : NEG * zz1;
        float zz2 = alc2 + ald + aec2; zz2 = zz2 > 0.f ? zz2 : NEG * zz2;
        float zz3 = alc3 + ald + aec3; zz3 = zz3 > 0.f ? zz3 : NEG * zz3;
        float e0 = __expf(zz0), e1 = __expf(zz1), e2 = __expf(zz2), e3 = __expf(zz3);
        s += (e0 + e1) + (e2 + e3);
        float2 f00 = __bfloat1622float2(*(__nv_bfloat162*)&uc0.x);
        float2 f01 = __bfloat1622float2(*(__nv_bfloat162*)&uc0.y);
        float2 f10 = __bfloat1622float2(*(__nv_bfloat162*)&uc1.x);
        float2 f11 = __bfloat1622float2(*(__nv_bfloat162*)&uc1.y);
        float2 f20 = __bfloat1622float2(*(__nv_bfloat162*)&uc2.x);
        float2 f21 = __bfloat1622float2(*(__nv_bfloat162*)&uc2.y);
        float2 f30 = __bfloat1622float2(*(__nv_bfloat162*)&uc3.x);
        float2 f31 = __bfloat1622float2(*(__nv_bfloat162*)&uc3.y);
        acc.x += f00.x * e0 + f10.x * e1 + f20.x * e2 + f30.x * e3;
        acc.y += f00.y * e0 + f10.y * e1 + f20.y * e2 + f30.y * e3;
        acc.z += f01.x * e0 + f11.x * e1 + f21.x * e2 + f31.x * e3;
        acc.w += f01.y * e0 + f11.y * e1 + f21.y * e2 + f31.y * e3;
        // rotate
        j = jn; jn = jnn;
        has0 = has1; has1 = has2;
        alc0 = aln0; alc1 = aln1; alc2 = aln2; alc3 = aln3;
        aec0 = aen0; aec1 = aen1; aec2 = aen2; aec3 = aen3;
        uc0 = un0; uc1 = un1; uc2 = un2; uc3 = un3;
        sn0 = snn0; sn1 = snn1; sn2 = snn2; sn3 = snn3;
    }
    for (; j < end; j++) {
        int sA = srcv[j];
        float aleA = alE2[j];
        float alsA = als2[sA];
        uint2 uA = xw[(size_t)sA * 32 + l];
        salE += aleA;
        float zA = alsA + ald + aleA; zA = zA > 0.f ? zA : NEG * zA;
        float eA = __expf(zA);
        s += eA;
        float2 fA0 = __bfloat1622float2(*(__nv_bfloat162*)&uA.x);
        float2 fA1 = __bfloat1622float2(*(__nv_bfloat162*)&uA.y);
        acc.x += fA0.x * eA; acc.y += fA0.y * eA; acc.z += fA1.x * eA; acc.w += fA1.y * eA;
    }
    // self loop
    float rd = 1.f / (float)max(end - beg, 1);
    float zs = myals + ald + salE * rd;
    zs = zs > 0.f ? zs : NEG * zs;
    float es = __expf(zs);
    s += es;
    uint2 uS = xw[(size_t)n * 32 + l];
    float2 fS0 = __bfloat1622float2(*(__nv_bfloat162*)&uS.x);
    float2 fS1 = __bfloat1622float2(*(__nv_bfloat162*)&uS.y);
    acc.x += fS0.x * es; acc.y += fS0.y * es; acc.z += fS1.x * es; acc.w += fS1.y * es;

    float inv = 1.f / (s + 1e-16f);
    float4 bb = ((const float4*)b2)[l];
    float4 o = make_float4(acc.x * inv + bb.x, acc.y * inv + bb.y,
                           acc.z * inv + bb.z, acc.w * inv + bb.w);
    ((float4*)g_out2)[(size_t)n * 32 + l] = o;
}

// Global mean pool: one block per graph; 512 threads = 4-way row split per feature.
__global__ void pool_kernel(float* __restrict__ out) {
    __shared__ float sm[4][128];
    int g = blockIdx.x;
    int f = threadIdx.x & 127;
    int part = threadIdx.x >> 7;
    int s = g_gptr[g], e = g_gptr[g + 1];
    float acc = 0.f;
    for (int n = s + part; n < e; n += 4) acc += g_out2[(size_t)n * OUT + f];
    sm[part][f] = acc;
    __syncthreads();
    if (part == 0)
        out[g * OUT + f] = (sm[0][f] + sm[1][f] + sm[2][f] + sm[3][f])
                           / fmaxf((float)(e - s), 1.f);
}

// ---------------- launch ----------------
extern "C" void kernel_launch(void* const* d_in, const int* in_sizes, int n_in,
                              void* d_out, int out_size) {
    const float* x     = (const float*)d_in[0];
    const int*   ei    = (const int*)d_in[1];
    const float* ea    = (const float*)d_in[2];
    const int*   batch = (const int*)d_in[3];
    const float* W1    = (const float*)d_in[4];
    const float* as1   = (const float*)d_in[5];
    const float* ad1   = (const float*)d_in[6];
    const float* ae1   = (const float*)d_in[7];
    const float* We1   = (const float*)d_in[8];
    const float* b1    = (const float*)d_in[9];
    const float* W2    = (const float*)d_in[10];
    const float* as2   = (const float*)d_in[11];
    const float* ad2   = (const float*)d_in[12];
    const float* ae2   = (const float*)d_in[13];
    const float* We2   = (const float*)d_in[14];
    const float* b2    = (const float*)d_in[15];
    float* out = (float*)d_out;

    bool fork = (g_s2 != 0) && (g_evF != 0) && (g_evJ != 0);

    if (fork) {
        cudaEventRecord(g_evF, 0);
        cudaStreamWaitEvent(g_s2, g_evF, 0);
        gemm1_kernel<<<(NN + G1_NODES - 1) / G1_NODES, 256, 0, g_s2>>>(x, W1, as1, ad1);
        cudaEventRecord(g_evJ, g_s2);
    }

    setup_kernel<<<NPAD / 256, 256>>>(We1, ae1, We2, ae2, batch);
    deg_kernel<<<(EE / 4 + 255) / 256, 256>>>(ei);
    scan_kernel<<<SCAN_BLOCKS, 1024>>>();
    scatter_kernel<<<(EE / 4 + 255) / 256, 256>>>(ei, ea);

    if (fork) {
        cudaStreamWaitEvent(0, g_evJ, 0);   // join: agg1 needs gemm1 outputs
    } else {
        gemm1_kernel<<<(NN + G1_NODES - 1) / G1_NODES, 256>>>(x, W1, as1, ad1);
    }

    agg1_kernel<<<NN / 8, 256>>>(b1);
    gemm2_kernel<<<(NN + G2_NODES - 1) / G2_NODES, 256>>>(W2, as2, ad2);
    agg2_kernel<<<NN / 8, 256>>>(b2);
    pool_kernel<<<GG, 512>>>(out);
}

// round 16
// speedup vs baseline: 1.0822x; 1.0822x over previous
#include <cuda_runtime.h>
#include <cuda_bf16.h>
#include <math.h>

// Problem constants (fixed by the reference)
#define NN 50000
#define EE 800000
#define FIN 128
#define ED 16
#define HID 64
#define OUT 128
#define GG 256
#define NEG 0.2f
#define NPAD 53248   // 52*1024, scan padding
#define SCAN_BLOCKS 52

// ---------------- device scratch (static, allocation-free) ----------------
__device__ int   g_deg[NPAD];
__device__ int   g_ptr[NN + 4];
__device__ int   g_cursor[NN];
__device__ int   g_bflag[SCAN_BLOCKS];       // lookback flags: bit30 = published
__device__ int   g_srcCSR[EE];
__device__ float g_alE1[EE * 8];     // per CSR slot, 8 heads (edge-only logit, layer1)
__device__ float g_alE2[EE];         // per CSR slot (edge-only logit, layer2)
__device__ __nv_bfloat162 g_xw1b[NN * 32];   // xw1 values, bf16 (64 feats/node)
__device__ float g_als1[NN * 8];
__device__ float g_ald1[NN * 8];
__device__ float g_h[NN * HID];              // layer-1 output (post ELU), fp32
__device__ __nv_bfloat162 g_xw2b[NN * 64];   // xw2 values, bf16 (128 feats/node)
__device__ float g_als2[NN];
__device__ float g_ald2[NN];
__device__ float g_out2[NN * OUT];
__device__ float g_M1[ED * 8];
__device__ float g_m2[ED];
__device__ int   g_gptr[GG + 1];

// Side stream + fork/join events (host-side resources only).
static cudaStream_t g_s2 = 0;
static cudaEvent_t  g_evF = 0, g_evJ = 0;
namespace {
struct StreamInit {
    StreamInit() {
        cudaStreamCreateWithFlags(&g_s2, cudaStreamNonBlocking);
        cudaEventCreateWithFlags(&g_evF, cudaEventDisableTiming);
        cudaEventCreateWithFlags(&g_evJ, cudaEventDisableTiming);
    }
};
StreamInit g_stream_init;
}

// packed fp32x2 FMA (sm_10x)
__device__ __forceinline__ void ffma2(unsigned long long& d,
                                      unsigned long long a, unsigned long long b) {
    asm("fma.rn.f32x2 %0, %1, %2, %0;" : "+l"(d) : "l"(a), "l"(b));
}
__device__ __forceinline__ unsigned long long pack2(float v) {
    unsigned long long r;
    asm("mov.b64 %0, {%1, %1};" : "=l"(r) : "r"(__float_as_uint(v)));
    return r;
}
__device__ __forceinline__ float2 unpack2(unsigned long long p) {
    unsigned int lo, hi;
    asm("mov.b64 {%0, %1}, %2;" : "=r"(lo), "=r"(hi) : "l"(p));
    return make_float2(__uint_as_float(lo), __uint_as_float(hi));
}
__device__ __forceinline__ void st_release(int* p, int v) {
    asm volatile("st.global.release.gpu.b32 [%0], %1;" :: "l"(p), "r"(v) : "memory");
}
__device__ __forceinline__ int ld_acquire(const int* p) {
    int v;
    asm volatile("ld.global.acquire.gpu.b32 %0, [%1];" : "=r"(v) : "l"(p) : "memory");
    return v;
}

// ---------------- kernels ----------------

// Fused setup: zero padded deg + scan flags + reduced attention matrices + graph offsets.
__global__ void setup_kernel(const float* __restrict__ We1, const float* __restrict__ ae1,
                             const float* __restrict__ We2, const float* __restrict__ ae2,
                             const int* __restrict__ batch) {
    int i = blockIdx.x * blockDim.x + threadIdx.x;
    if (i < NPAD) g_deg[i] = 0;
    if (i < SCAN_BLOCKS) g_bflag[i] = 0;
    if (i < 128) {
        int d = i >> 3, h = i & 7;
        float s = 0.f;
        #pragma unroll
        for (int c = 0; c < 8; c++) s += We1[d * 64 + h * 8 + c] * ae1[h * 8 + c];
        g_M1[d * 8 + h] = s;
    }
    if (i < ED) {
        float s = 0.f;
        for (int c = 0; c < OUT; c++) s += We2[i * OUT + c] * ae2[c];
        g_m2[i] = s;
    }
    if (i <= GG) {
        if (i == GG) g_gptr[GG] = NN;
        else {
            int lo = 0, hi = NN;
            while (lo < hi) {
                int mid = (lo + hi) >> 1;
                if (batch[mid] < i) lo = mid + 1; else hi = mid;
            }
            g_gptr[i] = lo;
        }
    }
}

// Degree count: int4 dst load, 4 independent RED chains per thread.
__global__ void deg_kernel(const int* __restrict__ ei) {
    int e4 = blockIdx.x * blockDim.x + threadIdx.x;
    if (e4 < EE / 4) {
        int4 d = ((const int4*)(ei + EE))[e4];
        atomicAdd(&g_deg[d.x], 1);
        atomicAdd(&g_deg[d.y], 1);
        atomicAdd(&g_deg[d.z], 1);
        atomicAdd(&g_deg[d.w], 1);
    }
}

// Parallel exclusive scan, decoupled lookback. 52 blocks x 1024 threads.
__global__ __launch_bounds__(1024) void scan_kernel() {
    int b = blockIdx.x, t = threadIdx.x;
    int gi = b * 1024 + t;
    int v = g_deg[gi];
    int incl = v;
    #pragma unroll
    for (int o = 1; o < 32; o <<= 1) {
        int u = __shfl_up_sync(0xffffffffu, incl, o);
        if ((t & 31) >= o) incl += u;
    }
    __shared__ int ws[32];
    __shared__ int s_tot, s_off;
    if ((t & 31) == 31) ws[t >> 5] = incl;
    __syncthreads();
    if (t < 32) {
        int wv = ws[t];
        int wincl = wv;
        #pragma unroll
        for (int o = 1; o < 32; o <<= 1) {
            int u = __shfl_up_sync(0xffffffffu, wincl, o);
            if (t >= o) wincl += u;
        }
        ws[t] = wincl - wv;
        if (t == 31) s_tot = wincl;
    }
    __syncthreads();
    if (t == 0) st_release(&g_bflag[b], s_tot | 0x40000000);
    if (t < 32) {
        int acc = 0;
        for (int p = t; p < b; p += 32) {
            int f;
            do { f = ld_acquire(&g_bflag[p]); } while (!(f & 0x40000000));
            acc += f & 0x3FFFFFFF;
        }
        #pragma unroll
        for (int o = 16; o > 0; o >>= 1) acc += __shfl_xor_sync(0xffffffffu, acc, o);
        if (t == 0) s_off = acc;
    }
    __syncthreads();
    int ptr = s_off + ws[t >> 5] + (incl - v);
    if (gi < NN) {
        g_ptr[gi] = ptr;
        g_cursor[gi] = ptr;
    }
    if (gi == NN) g_ptr[NN] = EE;
}

// Fused CSR scatter + edge-logit compute (f32x2-packed head math). 4 edges/thread.
__global__ __launch_bounds__(256) void scatter_kernel(const int* __restrict__ ei,
                                                      const float* __restrict__ ea) {
    __shared__ float sM1[ED * 8];
    __shared__ float sm2[ED];
    if (threadIdx.x < 128) sM1[threadIdx.x] = g_M1[threadIdx.x];
    if (threadIdx.x < ED) sm2[threadIdx.x] = g_m2[threadIdx.x];
    __syncthreads();
    int e4 = blockIdx.x * blockDim.x + threadIdx.x;
    if (e4 >= EE / 4) return;
    int4 s4 = ((const int4*)ei)[e4];
    int4 d4 = ((const int4*)(ei + EE))[e4];
    int srcs[4] = {s4.x, s4.y, s4.z, s4.w};
    int dsts[4] = {d4.x, d4.y, d4.z, d4.w};
    int pos[4];
    #pragma unroll
    for (int k = 0; k < 4; k++)
        pos[k] = atomicAdd(&g_cursor[dsts[k]], 1);
    const unsigned long long* sM1p = (const unsigned long long*)sM1;
    #pragma unroll
    for (int k = 0; k < 4; k++) {
        int e = e4 * 4 + k;
        const float4* p = (const float4*)(ea + (size_t)e * ED);
        float4 q0 = p[0], q1 = p[1], q2 = p[2], q3 = p[3];
        float av[16] = {q0.x, q0.y, q0.z, q0.w, q1.x, q1.y, q1.z, q1.w,
                        q2.x, q2.y, q2.z, q2.w, q3.x, q3.y, q3.z, q3.w};
        unsigned long long r01 = 0ull, r23 = 0ull, r45 = 0ull, r67 = 0ull;
        float r2 = 0.f;
        #pragma unroll
        for (int d = 0; d < ED; d++) {
            float a = av[d];
            unsigned long long ap = pack2(a);
            ffma2(r01, ap, sM1p[d * 4 + 0]);
            ffma2(r23, ap, sM1p[d * 4 + 1]);
            ffma2(r45, ap, sM1p[d * 4 + 2]);
            ffma2(r67, ap, sM1p[d * 4 + 3]);
            r2 += a * sm2[d];
        }
        int pk = pos[k];
        g_srcCSR[pk] = srcs[k];
        float2 f01 = unpack2(r01), f23 = unpack2(r23);
        float2 f45 = unpack2(r45), f67 = unpack2(r67);
        float4* o = (float4*)(g_alE1 + (size_t)pk * 8);
        o[0] = make_float4(f01.x, f01.y, f23.x, f23.y);
        o[1] = make_float4(f45.x, f45.y, f67.x, f67.y);
        g_alE2[pk] = r2;
    }
}

// xw1 = x @ W1 (bf16 out), plus per-node attention scalars als1/ald1 (fp32).
#define G1_NODES 64
__global__ __launch_bounds__(256) void gemm1_kernel(const float* __restrict__ x,
                             const float* __restrict__ W1,
                             const float* __restrict__ as1, const float* __restrict__ ad1) {
    __shared__ float xs[G1_NODES][FIN + 4];
    int n0 = blockIdx.x * G1_NODES;
    for (int idx = threadIdx.x; idx < G1_NODES * (FIN / 4); idx += 256) {
        int row = idx >> 5;
        int c4  = idx & 31;
        int n = n0 + row; if (n >= NN) n = NN - 1;
        float4 v = ((const float4*)(x + (size_t)n * FIN))[c4];
        *(float4*)&xs[row][c4 * 4] = v;
    }
    __syncthreads();
    int jg = threadIdx.x & 15;
    int ng = threadIdx.x >> 4;
    const ulonglong2* W1v = (const ulonglong2*)W1;
    unsigned long long a0[4], a1[4];
    #pragma unroll
    for (int i = 0; i < 4; i++) { a0[i] = 0ull; a1[i] = 0ull; }
    #pragma unroll 4
    for (int k = 0; k < FIN; k++) {
        ulonglong2 w = W1v[k * 16 + jg];
        #pragma unroll
        for (int i = 0; i < 4; i++) {
            unsigned long long xv = pack2(xs[ng * 4 + i][k]);
            ffma2(a0[i], xv, w.x);
            ffma2(a1[i], xv, w.y);
        }
    }
    float4 a_s = ((const float4*)as1)[jg];
    float4 a_d = ((const float4*)ad1)[jg];
    #pragma unroll
    for (int i = 0; i < 4; i++) {
        int n = n0 + ng * 4 + i;
        if (n >= NN) break;
        float2 lo = unpack2(a0[i]);
        float2 hi = unpack2(a1[i]);
        __nv_bfloat162 c0 = __float22bfloat162_rn(lo);
        __nv_bfloat162 c1 = __float22bfloat162_rn(hi);
        uint2 pk;
        pk.x = *(unsigned int*)&c0;
        pk.y = *(unsigned int*)&c1;
        ((uint2*)(g_xw1b + (size_t)n * 32))[jg] = pk;
        float ps = lo.x * a_s.x + lo.y * a_s.y + hi.x * a_s.z + hi.y * a_s.w;
        float pd = lo.x * a_d.x + lo.y * a_d.y + hi.x * a_d.z + hi.y * a_d.w;
        ps += __shfl_xor_sync(0xffffffffu, ps, 1);
        pd += __shfl_xor_sync(0xffffffffu, pd, 1);
        if ((threadIdx.x & 1) == 0) {
            int h = jg >> 1;
            g_als1[n * 8 + h] = ps;
            g_ald1[n * 8 + h] = pd;
        }
    }
}

// Layer-1 softmax + aggregation + ELU (self-loop folded). One warp per node,
// unroll-4 with srcv prefetch. HEAD-ALIGNED lanes: lane l computes the logit
// for head l>>2 (the head of its own features 2l,2l+1) — no shfl anywhere.
__global__ __launch_bounds__(256) void agg1_kernel(const float* __restrict__ b1) {
    int warp = (blockIdx.x * blockDim.x + threadIdx.x) >> 5;
    if (warp >= NN) return;
    int n = warp;
    int l = threadIdx.x & 31;
    int h = l >> 2;                            // head for features 2l, 2l+1
    const float* __restrict__ als1 = g_als1;
    const float* __restrict__ alE1 = g_alE1;
    const __nv_bfloat162* __restrict__ xw1b = g_xw1b;
    const int* __restrict__ srcv = g_srcCSR;

    float ald = g_ald1[n * 8 + h];
    float myals = als1[n * 8 + h];
    int beg = g_ptr[n], end = g_ptr[n + 1];

    float s = 0.f, salE = 0.f;
    float acc0 = 0.f, acc1 = 0.f;
    int j = beg;
    int p0 = 0, p1 = 0, p2 = 0, p3 = 0;
    if (j + 3 < end) { p0 = srcv[j]; p1 = srcv[j + 1]; p2 = srcv[j + 2]; p3 = srcv[j + 3]; }
    while (j + 3 < end) {
        int s0 = p0, s1 = p1, s2 = p2, s3 = p3;
        int jn = j + 4;
        if (jn + 3 < end) { p0 = srcv[jn]; p1 = srcv[jn + 1]; p2 = srcv[jn + 2]; p3 = srcv[jn + 3]; }
        float al0 = als1[s0 * 8 + h], al1 = als1[s1 * 8 + h];
        float al2 = als1[s2 * 8 + h], al3 = als1[s3 * 8 + h];
        float ae0 = alE1[(size_t)j * 8 + h],       ae1 = alE1[(size_t)(j + 1) * 8 + h];
        float ae2 = alE1[(size_t)(j + 2) * 8 + h], ae3 = alE1[(size_t)(j + 3) * 8 + h];
        __nv_bfloat162 v0 = xw1b[(size_t)s0 * 32 + l];
        __nv_bfloat162 v1 = xw1b[(size_t)s1 * 32 + l];
        __nv_bfloat162 v2 = xw1b[(size_t)s2 * 32 + l];
        __nv_bfloat162 v3 = xw1b[(size_t)s3 * 32 + l];
        salE += (ae0 + ae1) + (ae2 + ae3);
        float z0 = al0 + ald + ae0; z0 = z0 > 0.f ? z0 : NEG * z0;
        float z1 = al1 + ald + ae1; z1 = z1 > 0.f ? z1 : NEG * z1;
        float z2 = al2 + ald + ae2; z2 = z2 > 0.f ? z2 : NEG * z2;
        float z3 = al3 + ald + ae3; z3 = z3 > 0.f ? z3 : NEG * z3;
        float e0 = __expf(z0), e1 = __expf(z1), e2 = __expf(z2), e3 = __expf(z3);
        s += (e0 + e1) + (e2 + e3);
        float2 f0 = __bfloat1622float2(v0);
        float2 f1 = __bfloat1622float2(v1);
        float2 f2 = __bfloat1622float2(v2);
        float2 f3 = __bfloat1622float2(v3);
        acc0 += f0.x * e0 + f1.x * e1;
        acc1 += f0.y * e0 + f1.y * e1;
        acc0 += f2.x * e2 + f3.x * e3;
        acc1 += f2.y * e2 + f3.y * e3;
        j = jn;
    }
    for (; j < end; j++) {
        int sA = srcv[j];
        float alsA = als1[sA * 8 + h];
        float aleA = alE1[(size_t)j * 8 + h];
        __nv_bfloat162 vA = xw1b[(size_t)sA * 32 + l];
        salE += aleA;
        float zA = alsA + ald + aleA; zA = zA > 0.f ? zA : NEG * zA;
        float eA = __expf(zA);
        s += eA;
        float2 fA = __bfloat1622float2(vA);
        acc0 += fA.x * eA; acc1 += fA.y * eA;
    }
    // self loop: edge logit = mean of incoming edge logits (salE is full per-head sum)
    float rd = 1.f / (float)max(end - beg, 1);
    float zs = myals + ald + salE * rd;
    zs = zs > 0.f ? zs : NEG * zs;
    float es = __expf(zs);
    s += es;
    float2 fS = __bfloat1622float2(xw1b[(size_t)n * 32 + l]);
    acc0 += fS.x * es; acc1 += fS.y * es;
    // s is already the complete denominator for head h (this lane walked all edges)
    float2 bb = ((const float2*)b1)[l];
    float o0 = acc0 / (s + 1e-16f) + bb.x;
    float o1 = acc1 / (s + 1e-16f) + bb.y;
    o0 = o0 > 0.f ? o0 : (__expf(o0) - 1.f);   // ELU
    o1 = o1 > 0.f ? o1 : (__expf(o1) - 1.f);
    ((float2*)(g_h + (size_t)n * HID))[l] = make_float2(o0, o1);
}

// xw2 = h @ W2 (bf16 out) + als2/ald2 scalars. 32 nodes/block.
#define G2_NODES 32
__global__ __launch_bounds__(256) void gemm2_kernel(const float* __restrict__ W2,
                             const float* __restrict__ as2, const float* __restrict__ ad2) {
    __shared__ float hs2[G2_NODES][HID + 4];
    __shared__ float s_ps[G2_NODES][8];
    __shared__ float s_pd[G2_NODES][8];
    int n0 = blockIdx.x * G2_NODES;
    for (int idx = threadIdx.x; idx < G2_NODES * (HID / 4); idx += 256) {
        int row = idx >> 4, c4 = idx & 15;
        int n = n0 + row; if (n >= NN) n = NN - 1;
        float4 v = ((const float4*)(g_h + (size_t)n * HID))[c4];
        *(float4*)&hs2[row][c4 * 4] = v;
    }
    __syncthreads();
    int ndl = threadIdx.x & 7;
    int jg  = threadIdx.x >> 3;
    int wid = threadIdx.x >> 5;
    const ulonglong2* W2v = (const ulonglong2*)W2;
    unsigned long long a0[4], a1[4];
    #pragma unroll
    for (int i = 0; i < 4; i++) { a0[i] = 0ull; a1[i] = 0ull; }
    for (int kc = 0; kc < HID; kc += 4) {
        float4 hv4[4];
        #pragma unroll
        for (int i = 0; i < 4; i++)
            hv4[i] = *(const float4*)&hs2[ndl + 8 * i][kc];
        #pragma unroll
        for (int kk = 0; kk < 4; kk++) {
            ulonglong2 w = W2v[(kc + kk) * 32 + jg];
            #pragma unroll
            for (int i = 0; i < 4; i++) {
                unsigned long long hp = pack2(((const float*)&hv4[i])[kk]);
                ffma2(a0[i], hp, w.x);
                ffma2(a1[i], hp, w.y);
            }
        }
    }
    float4 a_s = ((const float4*)as2)[jg];
    float4 a_d = ((const float4*)ad2)[jg];
    #pragma unroll
    for (int i = 0; i < 4; i++) {
        int r = 8 * i + ndl;
        int n = n0 + r;
        float2 lo = unpack2(a0[i]);
        float2 hi = unpack2(a1[i]);
        float ps = lo.x * a_s.x + lo.y * a_s.y + hi.x * a_s.z + hi.y * a_s.w;
        float pd = lo.x * a_d.x + lo.y * a_d.y + hi.x * a_d.z + hi.y * a_d.w;
        ps += __shfl_xor_sync(0xffffffffu, ps, 8);
        pd += __shfl_xor_sync(0xffffffffu, pd, 8);
        ps += __shfl_xor_sync(0xffffffffu, ps, 16);
        pd += __shfl_xor_sync(0xffffffffu, pd, 16);
        if ((threadIdx.x & 24) == 0) {
            s_ps[r][wid] = ps;
            s_pd[r][wid] = pd;
        }
        if (n < NN) {
            __nv_bfloat162 c0 = __float22bfloat162_rn(lo);
            __nv_bfloat162 c1 = __float22bfloat162_rn(hi);
            uint2 pk;
            pk.x = *(unsigned int*)&c0;
            pk.y = *(unsigned int*)&c1;
            ((uint2*)(g_xw2b + (size_t)n * 64))[jg] = pk;
        }
    }
    __syncthreads();
    if (threadIdx.x < G2_NODES) {
        int n = n0 + threadIdx.x;
        if (n < NN) {
            float ps = 0.f, pd = 0.f;
            #pragma unroll
            for (int w = 0; w < 8; w++) { ps += s_ps[threadIdx.x][w]; pd += s_pd[threadIdx.x][w]; }
            g_als2[n] = ps;
            g_ald2[n] = pd;
        }
    }
}

// Layer-2 softmax + aggregation (self-loop folded). One warp per node, lane owns
// features 4l..4l+3; unroll-4 with srcv prefetch (bench-proven form).
__global__ __launch_bounds__(256) void agg2_kernel(const float* __restrict__ b2) {
    int warp = (blockIdx.x * blockDim.x + threadIdx.x) >> 5;
    if (warp >= NN) return;
    int n = warp;
    int l = threadIdx.x & 31;
    const uint2* __restrict__ xw = (const uint2*)g_xw2b;
    const float* __restrict__ als2 = g_als2;
    const float* __restrict__ alE2 = g_alE2;
    const int*   __restrict__ srcv = g_srcCSR;
    float ald = g_ald2[n];
    float myals = als2[n];
    int beg = g_ptr[n], end = g_ptr[n + 1];
    float s = 0.f, salE = 0.f;
    float4 acc = make_float4(0.f, 0.f, 0.f, 0.f);
    int j = beg;
    int p0 = 0, p1 = 0, p2 = 0, p3 = 0;
    if (j + 3 < end) { p0 = srcv[j]; p1 = srcv[j + 1]; p2 = srcv[j + 2]; p3 = srcv[j + 3]; }
    while (j + 3 < end) {
        int s0 = p0, s1 = p1, s2 = p2, s3 = p3;
        int jn = j + 4;
        if (jn + 3 < end) { p0 = srcv[jn]; p1 = srcv[jn + 1]; p2 = srcv[jn + 2]; p3 = srcv[jn + 3]; }
        float ae0 = alE2[j], ae1 = alE2[j + 1], ae2 = alE2[j + 2], ae3 = alE2[j + 3];
        float al0 = als2[s0], al1 = als2[s1], al2 = als2[s2], al3 = als2[s3];
        uint2 u0 = xw[(size_t)s0 * 32 + l];
        uint2 u1 = xw[(size_t)s1 * 32 + l];
        uint2 u2 = xw[(size_t)s2 * 32 + l];
        uint2 u3 = xw[(size_t)s3 * 32 + l];
        salE += (ae0 + ae1) + (ae2 + ae3);
        float z0 = al0 + ald + ae0; z0 = z0 > 0.f ? z0 : NEG * z0;
        float z1 = al1 + ald + ae1; z1 = z1 > 0.f ? z1 : NEG * z1;
        float z2 = al2 + ald + ae2; z2 = z2 > 0.f ? z2 : NEG * z2;
        float z3 = al3 + ald + ae3; z3 = z3 > 0.f ? z3 : NEG * z3;
        float e0 = __expf(z0), e1 = __expf(z1), e2 = __expf(z2), e3 = __expf(z3);
        s += (e0 + e1) + (e2 + e3);
        float2 f00 = __bfloat1622float2(*(__nv_bfloat162*)&u0.x);
        float2 f01 = __bfloat1622float2(*(__nv_bfloat162*)&u0.y);
        float2 f10 = __bfloat1622float2(*(__nv_bfloat162*)&u1.x);
        float2 f11 = __bfloat1622float2(*(__nv_bfloat162*)&u1.y);
        float2 f20 = __bfloat1622float2(*(__nv_bfloat162*)&u2.x);
        float2 f21 = __bfloat1622float2(*(__nv_bfloat162*)&u2.y);
        float2 f30 = __bfloat1622float2(*(__nv_bfloat162*)&u3.x);
        float2 f31 = __bfloat1622float2(*(__nv_bfloat162*)&u3.y);
        acc.x += f00.x * e0 + f10.x * e1 + f20.x * e2 + f30.x * e3;
        acc.y += f00.y * e0 + f10.y * e1 + f20.y * e2 + f30.y * e3;
        acc.z += f01.x * e0 + f11.x * e1 + f21.x * e2 + f31.x * e3;
        acc.w += f01.y * e0 + f11.y * e1 + f21.y * e2 + f31.y * e3;
        j = jn;
    }
    for (; j < end; j++) {
        int sA = srcv[j];
        float aleA = alE2[j];
        float alsA = als2[sA];
        uint2 uA = xw[(size_t)sA * 32 + l];
        salE += aleA;
        float zA = alsA + ald + aleA; zA = zA > 0.f ? zA : NEG * zA;
        float eA = __expf(zA);
        s += eA;
        float2 fA0 = __bfloat1622float2(*(__nv_bfloat162*)&uA.x);
        float2 fA1 = __bfloat1622float2(*(__nv_bfloat162*)&uA.y);
        acc.x += fA0.x * eA; acc.y += fA0.y * eA; acc.z += fA1.x * eA; acc.w += fA1.y * eA;
    }
    // self loop
    float rd = 1.f / (float)max(end - beg, 1);
    float zs = myals + ald + salE * rd;
    zs = zs > 0.f ? zs : NEG * zs;
    float es = __expf(zs);
    s += es;
    uint2 uS = xw[(size_t)n * 32 + l];
    float2 fS0 = __bfloat1622float2(*(__nv_bfloat162*)&uS.x);
    float2 fS1 = __bfloat1622float2(*(__nv_bfloat162*)&uS.y);
    acc.x += fS0.x * es; acc.y += fS0.y * es; acc.z += fS1.x * es; acc.w += fS1.y * es;

    float inv = 1.f / (s + 1e-16f);
    float4 bb = ((const float4*)b2)[l];
    float4 o = make_float4(acc.x * inv + bb.x, acc.y * inv + bb.y,
                           acc.z * inv + bb.z, acc.w * inv + bb.w);
    ((float4*)g_out2)[(size_t)n * 32 + l] = o;
}

// Global mean pool: one block per graph; lane owns a float4 of the 128 features,
// 8-way row split across the block (256 threads), vectorized loads.
__global__ void pool_kernel(float* __restrict__ out) {
    __shared__ float4 sm[8][32];
    int g = blockIdx.x;
    int f4 = threadIdx.x & 31;      // which float4 of the row (32 x 4 = 128)
    int part = threadIdx.x >> 5;    // 0..7
    int s = g_gptr[g], e = g_gptr[g + 1];
    const float4* o2 = (const float4*)g_out2;
    float4 acc = make_float4(0.f, 0.f, 0.f, 0.f);
    for (int n = s + part; n < e; n += 8) {
        float4 v = o2[(size_t)n * 32 + f4];
        acc.x += v.x; acc.y += v.y; acc.z += v.z; acc.w += v.w;
    }
    sm[part][f4] = acc;
    __syncthreads();
    if (part == 0) {
        #pragma unroll
        for (int p = 1; p < 8; p++) {
            float4 v = sm[p][f4];
            acc.x += v.x; acc.y += v.y; acc.z += v.z; acc.w += v.w;
        }
        float inv = 1.f / fmaxf((float)(e - s), 1.f);
        float4 o = make_float4(acc.x * inv, acc.y * inv, acc.z * inv, acc.w * inv);
        ((float4*)(out + (size_t)g * OUT))[f4] = o;
    }
}

// ---------------- launch ----------------
extern "C" void kernel_launch(void* const* d_in, const int* in_sizes, int n_in,
                              void* d_out, int out_size) {
    const float* x     = (const float*)d_in[0];
    const int*   ei    = (const int*)d_in[1];
    const float* ea    = (const float*)d_in[2];
    const int*   batch = (const int*)d_in[3];
    const float* W1    = (const float*)d_in[4];
    const float* as1   = (const float*)d_in[5];
    const float* ad1   = (const float*)d_in[6];
    const float* ae1   = (const float*)d_in[7];
    const float* We1   = (const float*)d_in[8];
    const float* b1    = (const float*)d_in[9];
    const float* W2    = (const float*)d_in[10];
    const float* as2   = (const float*)d_in[11];
    const float* ad2   = (const float*)d_in[12];
    const float* ae2   = (const float*)d_in[13];
    const float* We2   = (const float*)d_in[14];
    const float* b2    = (const float*)d_in[15];
    float* out = (float*)d_out;

    bool fork = (g_s2 != 0) && (g_evF != 0) && (g_evJ != 0);

    if (fork) {
        cudaEventRecord(g_evF, 0);
        cudaStreamWaitEvent(g_s2, g_evF, 0);
        gemm1_kernel<<<(NN + G1_NODES - 1) / G1_NODES, 256, 0, g_s2>>>(x, W1, as1, ad1);
        cudaEventRecord(g_evJ, g_s2);
    }

    setup_kernel<<<NPAD / 256, 256>>>(We1, ae1, We2, ae2, batch);
    deg_kernel<<<(EE / 4 + 255) / 256, 256>>>(ei);
    scan_kernel<<<SCAN_BLOCKS, 1024>>>();
    scatter_kernel<<<(EE / 4 + 255) / 256, 256>>>(ei, ea);

    if (fork) {
        cudaStreamWaitEvent(0, g_evJ, 0);   // join: agg1 needs gemm1 outputs
    } else {
        gemm1_kernel<<<(NN + G1_NODES - 1) / G1_NODES, 256>>>(x, W1, as1, ad1);
    }

    agg1_kernel<<<NN / 8, 256>>>(b1);
    gemm2_kernel<<<(NN + G2_NODES - 1) / G2_NODES, 256>>>(W2, as2, ad2);
    agg2_kernel<<<NN / 8, 256>>>(b2);
    pool_kernel<<<GG, 256>>>(out);
}